// round 1
// baseline (speedup 1.0000x reference)
#include <cuda_runtime.h>

#define HW 16384
#define WD 128

// Scratch (allocation-free rule: __device__ globals)
__device__ float g_est1[2 * 128 * HW];   // 16 MB
__device__ float g_est2[2 * 128 * HW];   // 16 MB
__device__ float g_off [2 * 18  * HW];   // 2.25 MB
__device__ float g_wt  [9 * 128 * 128];  // w_def transposed to [k][c][o]

// ---------------------------------------------------------------------------
// Direct 3x3 conv, stride 1, pad 1, NCHW. H=W=128 hardcoded.
// Block: 128 threads, output tile 16(h) x 32(w), each thread 2x2 pixels,
// OC_B output channels per block (register-blocked).
// CONCAT=true treats channels [0,128) from in0 and [128,256) from in1.
// ---------------------------------------------------------------------------
template <int C_IN, int OC_B, bool RELU, bool CONCAT>
__global__ __launch_bounds__(128) void conv3x3_k(
    const float* __restrict__ in0, const float* __restrict__ in1,
    const float* __restrict__ wt, float* __restrict__ out,
    int C_out, int n_ocb)
{
    __shared__ float st[18 * 34];
    __shared__ float sw[OC_B * 9];

    const int tid = threadIdx.x;
    const int tx  = tid & 15;        // 16 threads across W (2 px each)
    const int ty  = tid >> 4;        // 8  threads across H (2 px each)
    const int w0  = blockIdx.x * 32;
    const int h0  = blockIdx.y * 16;
    const int b   = blockIdx.z / n_ocb;
    const int ocb = blockIdx.z % n_ocb;

    float acc[OC_B][4];
#pragma unroll
    for (int o = 0; o < OC_B; o++)
#pragma unroll
        for (int p = 0; p < 4; p++) acc[o][p] = 0.f;

    for (int c = 0; c < C_IN; ++c) {
        const float* plane;
        if (CONCAT) {
            plane = (c < 128) ? in0 + (size_t)(b * 128 + c) * HW
                              : in1 + (size_t)(b * 128 + (c - 128)) * HW;
        } else {
            plane = in0 + (size_t)(b * C_IN + c) * HW;
        }

        // stage 18x34 input tile (halo 1) for this channel
        for (int i = tid; i < 18 * 34; i += 128) {
            int r  = i / 34;
            int cc = i - r * 34;
            int gh = h0 - 1 + r;
            int gw = w0 - 1 + cc;
            float v = 0.f;
            if ((unsigned)gh < 128u && (unsigned)gw < 128u)
                v = __ldg(plane + gh * WD + gw);
            st[i] = v;
        }
        // stage OC_B x 9 weights for this input channel
        if (tid < OC_B * 9) {
            int o = ocb * OC_B + tid / 9;
            sw[tid] = (o < C_out) ? wt[((size_t)o * C_IN + c) * 9 + (tid % 9)]
                                  : 0.f;
        }
        __syncthreads();

        float iv[4][4];
#pragma unroll
        for (int yy = 0; yy < 4; yy++)
#pragma unroll
            for (int xx = 0; xx < 4; xx++)
                iv[yy][xx] = st[(ty * 2 + yy) * 34 + tx * 2 + xx];

#pragma unroll
        for (int o = 0; o < OC_B; o++) {
#pragma unroll
            for (int ky = 0; ky < 3; ky++)
#pragma unroll
                for (int kx = 0; kx < 3; kx++) {
                    float wv = sw[o * 9 + ky * 3 + kx];
                    acc[o][0] += iv[ky    ][kx    ] * wv;
                    acc[o][1] += iv[ky    ][kx + 1] * wv;
                    acc[o][2] += iv[ky + 1][kx    ] * wv;
                    acc[o][3] += iv[ky + 1][kx + 1] * wv;
                }
        }
        __syncthreads();
    }

    const int ph = h0 + ty * 2, pw = w0 + tx * 2;
#pragma unroll
    for (int o = 0; o < OC_B; o++) {
        int oc = ocb * OC_B + o;
        if (oc >= C_out) break;
        float* op = out + (size_t)(b * C_out + oc) * HW + ph * WD + pw;
        float v0 = acc[o][0], v1 = acc[o][1], v2 = acc[o][2], v3 = acc[o][3];
        if (RELU) {
            v0 = fmaxf(v0, 0.f); v1 = fmaxf(v1, 0.f);
            v2 = fmaxf(v2, 0.f); v3 = fmaxf(v3, 0.f);
        }
        op[0]      = v0; op[1]      = v1;
        op[WD]     = v2; op[WD + 1] = v3;
    }
}

// ---------------------------------------------------------------------------
// Transpose w_def [O,C,3,3] -> g_wt [k][c][o]  (o contiguous for the deform
// kernel's coalesced SMEM staging)
// ---------------------------------------------------------------------------
__global__ void transpose_wdef(const float* __restrict__ w, float* __restrict__ wtp)
{
    int idx = blockIdx.x * 256 + threadIdx.x;
    if (idx >= 9 * 128 * 128) return;
    int o = idx & 127;
    int c = (idx >> 7) & 127;
    int k = idx >> 14;
    wtp[idx] = w[((size_t)o * 128 + c) * 9 + k];
}

// ---------------------------------------------------------------------------
// Fused deformable conv: bilinear gather from reference_features (L2-resident,
// 8MB/batch) + 1152x64 per-pixel matvec.
// Block: 128 threads = 128 pixels (8h x 16w), 64 output channels (grid z split
// into 2 oc-blocks). Per k: stage 128c x 64o weights (32 KB) in SMEM, then
// c-loop: 4 LDG gathers + 64 FFMA via float4 broadcast reads.
// ---------------------------------------------------------------------------
__global__ __launch_bounds__(128) void deform_k(
    const float* __restrict__ ref, const float* __restrict__ off,
    const float* __restrict__ wtp, float* __restrict__ out)
{
    __shared__ float swt[128 * 64];  // [c][o] for current k, 32 KB

    const int tid = threadIdx.x;
    const int w = blockIdx.x * 16 + (tid & 15);
    const int h = blockIdx.y * 8  + (tid >> 4);
    const int b  = blockIdx.z >> 1;
    const int ob = blockIdx.z & 1;

    float acc[64];
#pragma unroll
    for (int j = 0; j < 64; j++) acc[j] = 0.f;

    const float* offp = off + (size_t)b * 18 * HW + h * WD + w;
    const float* pb   = ref + (size_t)b * 128 * HW;

    for (int k = 0; k < 9; ++k) {
        // --- bilinear sampling parameters for this tap (per-corner validity,
        //     matching torchvision/reference semantics: zero outside) ---
        float dy = __ldg(offp + (2 * k)     * HW);
        float dx = __ldg(offp + (2 * k + 1) * HW);
        float py = (float)(h + (k / 3) - 1) + dy;
        float px = (float)(w + (k % 3) - 1) + dx;
        float y0f = floorf(py), x0f = floorf(px);
        float wy = py - y0f, wx = px - x0f;
        int y0 = (int)y0f, x0 = (int)x0f;
        int y1 = y0 + 1,   x1 = x0 + 1;
        bool vy0 = (unsigned)y0 < 128u, vy1 = (unsigned)y1 < 128u;
        bool vx0 = (unsigned)x0 < 128u, vx1 = (unsigned)x1 < 128u;
        int y0c = min(max(y0, 0), 127), y1c = min(max(y1, 0), 127);
        int x0c = min(max(x0, 0), 127), x1c = min(max(x1, 0), 127);
        float w00 = (1.f - wy) * (1.f - wx) * ((vy0 && vx0) ? 1.f : 0.f);
        float w01 = (1.f - wy) * wx         * ((vy0 && vx1) ? 1.f : 0.f);
        float w10 = wy * (1.f - wx)         * ((vy1 && vx0) ? 1.f : 0.f);
        float w11 = wy * wx                 * ((vy1 && vx1) ? 1.f : 0.f);
        int o00 = y0c * WD + x0c, o01 = y0c * WD + x1c;
        int o10 = y1c * WD + x0c, o11 = y1c * WD + x1c;

        // --- stage weights for this tap: swt[c*64 + j] = wt[k][c][ob*64+j] ---
        __syncthreads();  // previous iteration's reads done
        for (int i = tid * 4; i < 8192; i += 128 * 4) {
            int c = i >> 6, j = i & 63;
            *(float4*)(swt + i) =
                *(const float4*)(wtp + (size_t)k * 16384 + c * 128 + ob * 64 + j);
        }
        __syncthreads();

        // --- channel loop: gather + accumulate 64 output channels ---
#pragma unroll 4
        for (int c = 0; c < 128; ++c) {
            const float* pl = pb + (size_t)c * HW;
            float s = w00 * __ldg(pl + o00) + w01 * __ldg(pl + o01)
                    + w10 * __ldg(pl + o10) + w11 * __ldg(pl + o11);
            const float4* wr = (const float4*)(swt + c * 64);
#pragma unroll
            for (int j = 0; j < 16; j++) {
                float4 wv = wr[j];
                acc[4 * j + 0] += s * wv.x;
                acc[4 * j + 1] += s * wv.y;
                acc[4 * j + 2] += s * wv.z;
                acc[4 * j + 3] += s * wv.w;
            }
        }
    }

    float* op = out + ((size_t)b * 128 + ob * 64) * HW + h * WD + w;
#pragma unroll
    for (int j = 0; j < 64; j++) op[(size_t)j * HW] = acc[j];
}

// ---------------------------------------------------------------------------
extern "C" void kernel_launch(void* const* d_in, const int* in_sizes, int n_in,
                              void* d_out, int out_size)
{
    const float* x  = (const float*)d_in[0];  // input_features
    const float* rf = (const float*)d_in[1];  // reference_features
    const float* w1 = (const float*)d_in[2];  // w_est1 [128,256,3,3]
    const float* w2 = (const float*)d_in[3];  // w_est2 [128,128,3,3]
    const float* wo = (const float*)d_in[4];  // w_off  [18,128,3,3]
    const float* wd = (const float*)d_in[5];  // w_def  [128,128,3,3]
    float* out = (float*)d_out;

    const int B = in_sizes[0] / (128 * HW);   // 2

    float *e1, *e2, *of, *wtp;
    cudaGetSymbolAddress((void**)&e1,  g_est1);
    cudaGetSymbolAddress((void**)&e2,  g_est2);
    cudaGetSymbolAddress((void**)&of,  g_off);
    cudaGetSymbolAddress((void**)&wtp, g_wt);

    dim3 blk(128);

    // est = relu(conv(concat(x, rf), w_est1))
    conv3x3_k<256, 8, true,  true ><<<dim3(4, 8, B * 16), blk>>>(x,  rf,      w1, e1, 128, 16);
    // est = relu(conv(est, w_est2))
    conv3x3_k<128, 8, true,  false><<<dim3(4, 8, B * 16), blk>>>(e1, nullptr, w2, e2, 128, 16);
    // offset = conv(est, w_off)
    conv3x3_k<128, 6, false, false><<<dim3(4, 8, B * 3),  blk>>>(e2, nullptr, wo, of, 18,  3);
    // weight transpose for deform (independent; tiny)
    transpose_wdef<<<(9 * 128 * 128 + 255) / 256, 256>>>(wd, wtp);
    // out = deform_conv2d(rf, offset, w_def)
    deform_k<<<dim3(8, 16, B * 2), blk>>>(rf, of, wtp, out);
}